// round 6
// baseline (speedup 1.0000x reference)
#include <cuda_runtime.h>
#include <cstdint>

// WeightedAggregator: out[b, :] = sum_k (w[b,k] / sum_j w[b,j]) * features[idx[b,k], :]
// B = 50000, K = 16, D = 128 (fp32). One warp per output row; one float4 per lane.
// neigh_idx is int32 (JAX demotes int64 without x64 mode).
//
// R6: L2 residency via createpolicy + cache_hint (the inline .L2::evict_last
// qualifier requires 256-bit vectors on sm_103a ptxas; the cache_hint form
// works with v4.f32). Features -> evict_last (re-referenced ~1.6x),
// output stores -> evict_first (write-once).

#define K_NEIGH 16
#define FEAT_D 128

__device__ __forceinline__ uint64_t policy_evict_last() {
    uint64_t p;
    asm("createpolicy.fractional.L2::evict_last.b64 %0, 1.0;" : "=l"(p));
    return p;
}

__device__ __forceinline__ uint64_t policy_evict_first() {
    uint64_t p;
    asm("createpolicy.fractional.L2::evict_first.b64 %0, 1.0;" : "=l"(p));
    return p;
}

__device__ __forceinline__ float4 ldg_nc_hint(const float4* p, uint64_t pol) {
    float4 v;
    asm("ld.global.nc.L2::cache_hint.v4.f32 {%0,%1,%2,%3}, [%4], %5;"
        : "=f"(v.x), "=f"(v.y), "=f"(v.z), "=f"(v.w)
        : "l"(p), "l"(pol));
    return v;
}

__device__ __forceinline__ void stg_hint(float4* p, float4 v, uint64_t pol) {
    asm volatile("st.global.L2::cache_hint.v4.f32 [%0], {%1,%2,%3,%4}, %5;"
                 :: "l"(p), "f"(v.x), "f"(v.y), "f"(v.z), "f"(v.w), "l"(pol)
                 : "memory");
}

__global__ __launch_bounds__(256)
void weighted_agg_kernel(const float* __restrict__ features,
                         const float* __restrict__ neigh_w,
                         const int* __restrict__ neigh_idx,
                         float* __restrict__ out,
                         int B)
{
    const int gtid = blockIdx.x * blockDim.x + threadIdx.x;
    const int row  = gtid >> 5;          // warp id = output row
    const int lane = threadIdx.x & 31;
    if (row >= B) return;

    const uint64_t pol_last  = policy_evict_last();
    const uint64_t pol_first = policy_evict_first();

    // Lanes 0..15 hold this row's weight + index; others hold 0.
    float w  = 0.0f;
    int   ix = 0;
    if (lane < K_NEIGH) {
        w  = neigh_w  [row * K_NEIGH + lane];
        ix = neigh_idx[row * K_NEIGH + lane];
    }

    // Warp-wide sum of weights (lanes >= 16 contribute 0).
    float s = w;
    #pragma unroll
    for (int off = 16; off > 0; off >>= 1)
        s += __shfl_xor_sync(0xffffffffu, s, off);
    const float inv = 1.0f / s;

    const float4* __restrict__ feat4 = (const float4*)features;

    // Phase 1: batch all 16 gather loads (asm preserves issue order -> MLP=16).
    // Each warp-load = 4 x 128B lines, fully coalesced.
    float4 f[K_NEIGH];
    #pragma unroll
    for (int k = 0; k < K_NEIGH; k++) {
        const int ik = __shfl_sync(0xffffffffu, ix, k);
        f[k] = ldg_nc_hint(feat4 + (long long)ik * (FEAT_D / 4) + lane, pol_last);
    }

    // Phase 2: weighted accumulation, two independent FFMA chains.
    float4 a0 = make_float4(0.f, 0.f, 0.f, 0.f);
    float4 a1 = make_float4(0.f, 0.f, 0.f, 0.f);
    #pragma unroll
    for (int k = 0; k < K_NEIGH; k += 2) {
        const float w0 = __shfl_sync(0xffffffffu, w, k);
        const float w1 = __shfl_sync(0xffffffffu, w, k + 1);
        a0.x += w0 * f[k].x;     a1.x += w1 * f[k + 1].x;
        a0.y += w0 * f[k].y;     a1.y += w1 * f[k + 1].y;
        a0.z += w0 * f[k].z;     a1.z += w1 * f[k + 1].z;
        a0.w += w0 * f[k].w;     a1.w += w1 * f[k + 1].w;
    }

    float4 r;
    r.x = (a0.x + a1.x) * inv;
    r.y = (a0.y + a1.y) * inv;
    r.z = (a0.z + a1.z) * inv;
    r.w = (a0.w + a1.w) * inv;

    stg_hint((float4*)out + (long long)row * (FEAT_D / 4) + lane, r, pol_first);
}

extern "C" void kernel_launch(void* const* d_in, const int* in_sizes, int n_in,
                              void* d_out, int out_size)
{
    const float* features  = (const float*)d_in[0];   // [N_NODES, 128] fp32
    const float* neigh_w   = (const float*)d_in[1];   // [B, 16] fp32
    const int*   neigh_idx = (const int*)d_in[2];     // [B, 16] int32
    float*       out       = (float*)d_out;           // [B, 128] fp32

    const int B = in_sizes[1] / K_NEIGH;   // 50000

    const int threads = 256;               // 8 warps/block -> 8 rows/block
    const int rows_per_block = threads / 32;
    const int blocks = (B + rows_per_block - 1) / rows_per_block;

    weighted_agg_kernel<<<blocks, threads>>>(features, neigh_w, neigh_idx, out, B);
}